// round 2
// baseline (speedup 1.0000x reference)
#include <cuda_runtime.h>
#include <cstdint>

// ---------------------------------------------------------------------------
// TemporalAttentionPooling (GB300 / sm_103a)
//   scores = tanh(x @ W1 + b1) @ W2 + b2            (N,)    MLP: 128 -> 32 -> 1
//   per-segment (sorted person_ids) stable softmax -> weights
//   pooled[p] = sum_i w_i * x_i                     (P, 128)
//   second output: pooled_pids = arange(P)          (P,)  written as float(p)
//
// Strategy:
//   - boundary kernels build seg_start[P+1] in __device__ scratch
//   - one fused persistent kernel: block processes whole segments; warp-per-row
//     score MLP with W1 held in registers as f32x2 pairs (fma.rn.f32x2),
//     online softmax (chunked, robust to any segment length), pooling pass
//     re-reads the segment's x rows from L1 (single DRAM pass over x).
// ---------------------------------------------------------------------------

#define MAX_P 20001
__device__ int g_seg_start[MAX_P];

static __device__ __forceinline__ unsigned long long f2pack(float lo, float hi) {
    unsigned long long r;
    asm("mov.b64 %0, {%1, %2};" : "=l"(r) : "f"(lo), "f"(hi));
    return r;
}
static __device__ __forceinline__ void f2unpack(unsigned long long v, float& lo, float& hi) {
    asm("mov.b64 {%0, %1}, %2;" : "=f"(lo), "=f"(hi) : "l"(v));
}
static __device__ __forceinline__ unsigned long long ffma2(unsigned long long a,
                                                           unsigned long long b,
                                                           unsigned long long c) {
    unsigned long long d;
    asm("fma.rn.f32x2 %0, %1, %2, %3;" : "=l"(d) : "l"(a), "l"(b), "l"(c));
    return d;
}
static __device__ __forceinline__ unsigned long long fadd2(unsigned long long a,
                                                           unsigned long long b) {
    unsigned long long d;
    asm("add.rn.f32x2 %0, %1, %2;" : "=l"(d) : "l"(a), "l"(b));
    return d;
}

// Block-wide reduce over 128 threads. red must hold >= 5 floats.
static __device__ __forceinline__ float blk_reduce(float v, float* red, int tid, bool domax) {
    int lane = tid & 31, wid = tid >> 5;
#pragma unroll
    for (int o = 16; o > 0; o >>= 1) {
        float u = __shfl_xor_sync(0xffffffffu, v, o);
        v = domax ? fmaxf(v, u) : (v + u);
    }
    __syncthreads();               // protects red reuse + publishes prior smem writes
    if (lane == 0) red[wid] = v;
    __syncthreads();
    if (tid == 0) {
        float r = red[0];
#pragma unroll
        for (int w = 1; w < 4; w++) r = domax ? fmaxf(r, red[w]) : (r + red[w]);
        red[4] = r;
    }
    __syncthreads();
    return red[4];
}

// ---- boundary kernels ------------------------------------------------------
__global__ void k_init_bounds(int P, int n) {
    int i = blockIdx.x * blockDim.x + threadIdx.x;
    if (i <= P) g_seg_start[i] = n;
}
__global__ void k_bounds(const int* __restrict__ pid, int n) {
    int i = blockIdx.x * blockDim.x + threadIdx.x;
    if (i >= n) return;
    int cur  = pid[i];
    int prev = (i == 0) ? -1 : pid[i - 1];
    for (int q = prev + 1; q <= cur; ++q) g_seg_start[q] = i;
}
__global__ void k_pids(float* __restrict__ out, int P) {
    int p = blockIdx.x * blockDim.x + threadIdx.x;
    if (p < P) out[p] = (float)p;
}

// ---- fused main kernel -----------------------------------------------------
#define CHUNK 512

__global__ void __launch_bounds__(128, 3)
seg_attn_pool(const float* __restrict__ x,
              const float* __restrict__ W1,   // (128, 32) row-major
              const float* __restrict__ b1,   // (32,)
              const float* __restrict__ W2,   // (32,)
              const float* __restrict__ b2,   // (1,)
              float* __restrict__ out,        // (P, 128)
              int P) {
    __shared__ __align__(16) float xbuf[4][128];   // per-warp row stage
    __shared__ float sc[CHUNK];                    // chunk scores -> exp weights
    __shared__ float red[5];

    const int tid  = threadIdx.x;
    const int wid  = tid >> 5;
    const int lane = tid & 31;
    const float NEG_INF = __int_as_float(0xff800000u);

    // Load W1 column `lane` into registers as 64 f32x2 pairs (d-pairs).
    unsigned long long w1p[64];
#pragma unroll
    for (int q = 0; q < 64; q++) {
        float lo = W1[(2 * q) * 32 + lane];
        float hi = W1[(2 * q + 1) * 32 + lane];
        w1p[q] = f2pack(lo, hi);
    }
    const float w2j = W2[lane];
    const float b2s = b2[0];
    const unsigned long long b1pair = f2pack(b1[lane], 0.0f);

    for (int p = blockIdx.x; p < P; p += gridDim.x) {
        const int s0 = g_seg_start[p];
        const int s1 = g_seg_start[p + 1];

        float M = NEG_INF;   // running max (replicated block-wide)
        float S = 0.0f;      // running sum of exp
        float acc = 0.0f;    // running pooled accumulator for dim `tid`

        for (int c0 = s0; c0 < s1; c0 += CHUNK) {
            const int cnt = min(CHUNK, s1 - c0);

            // --- scores: warp-per-row ---
            for (int ci = wid; ci < cnt; ci += 4) {
                const float* xrow = x + (size_t)(c0 + ci) * 128;
                float4 xv = reinterpret_cast<const float4*>(xrow)[lane];
                reinterpret_cast<float4*>(xbuf[wid])[lane] = xv;
                __syncwarp();

                unsigned long long a0 = b1pair, a1 = 0ull, a2 = 0ull, a3 = 0ull;
                const ulonglong2* xb = reinterpret_cast<const ulonglong2*>(xbuf[wid]);
#pragma unroll
                for (int k = 0; k < 32; k++) {
                    ulonglong2 v = xb[k];           // broadcast LDS.128: 4 x-values
                    if (k & 1) {
                        a2 = ffma2(v.x, w1p[2 * k],     a2);
                        a3 = ffma2(v.y, w1p[2 * k + 1], a3);
                    } else {
                        a0 = ffma2(v.x, w1p[2 * k],     a0);
                        a1 = ffma2(v.y, w1p[2 * k + 1], a1);
                    }
                }
                unsigned long long t = fadd2(fadd2(a0, a2), fadd2(a1, a3));
                float lo, hi;
                f2unpack(t, lo, hi);
                float h  = tanhf(lo + hi);
                float sv = h * w2j;
#pragma unroll
                for (int o = 16; o > 0; o >>= 1)
                    sv += __shfl_xor_sync(0xffffffffu, sv, o);
                if (lane == 0) sc[ci] = sv + b2s;
                __syncwarp();                       // xbuf WAR before next row
            }
            __syncthreads();

            // --- chunk max, merge into running max ---
            float lm = NEG_INF;
            for (int i = tid; i < cnt; i += 128) lm = fmaxf(lm, sc[i]);
            float mC   = blk_reduce(lm, red, tid, true);
            float newM = fmaxf(M, mC);
            float scale = expf(M - newM);           // M==-inf on first chunk -> 0

            // --- exponentials + chunk sum (write e back into sc) ---
            float ls = 0.0f;
            for (int i = tid; i < cnt; i += 128) {
                float e = expf(sc[i] - newM);
                sc[i] = e;
                ls += e;
            }
            float sC = blk_reduce(ls, red, tid, false);  // syncs publish sc[]
            S = S * scale + sC;
            M = newM;

            // --- pooling: thread `tid` owns dim tid; x rows are L1-hot ---
            const float* xc = x + (size_t)c0 * 128 + tid;
            float p0 = 0.f, p1 = 0.f, p2 = 0.f, p3 = 0.f;
            int i = 0;
            for (; i + 4 <= cnt; i += 4) {
                p0 += sc[i]     * xc[(size_t)(i)     * 128];
                p1 += sc[i + 1] * xc[(size_t)(i + 1) * 128];
                p2 += sc[i + 2] * xc[(size_t)(i + 2) * 128];
                p3 += sc[i + 3] * xc[(size_t)(i + 3) * 128];
            }
            for (; i < cnt; i++) p0 += sc[i] * xc[(size_t)i * 128];
            acc = acc * scale + ((p0 + p1) + (p2 + p3));

            __syncthreads();                        // sc reuse next chunk
        }

        float denom = (S > 0.0f) ? S : 1.0f;        // empty segment -> 0/1 = 0
        out[(size_t)p * 128 + tid] = acc / denom;
    }
}

// ---------------------------------------------------------------------------
extern "C" void kernel_launch(void* const* d_in, const int* in_sizes, int n_in,
                              void* d_out, int out_size) {
    const float* x   = (const float*)d_in[0];
    const int*   pid = (const int*)  d_in[1];
    const float* W1  = (const float*)d_in[2];
    const float* b1  = (const float*)d_in[3];
    const float* W2  = (const float*)d_in[4];
    const float* b2  = (const float*)d_in[5];
    float* out = (float*)d_out;

    const int n = in_sizes[1];       // N (person_ids count)
    const int D = 128;

    // Output layout: concat(pooled (P,D), pooled_pids (P,)) -> P*(D+1) elems.
    int P;
    bool has_pids;
    if (out_size % (D + 1) == 0) {
        P = out_size / (D + 1);
        has_pids = true;
    } else {
        P = out_size / D;
        has_pids = false;
    }
    if (P > MAX_P - 1) P = MAX_P - 1;   // scratch guard (never hits for this problem)

    k_init_bounds<<<(P + 1 + 255) / 256, 256>>>(P, n);
    k_bounds<<<(n + 255) / 256, 256>>>(pid, n);

    int grid = 456;                   // ~3 persistent blocks per SM (152 SMs)
    if (grid > P) grid = P;
    seg_attn_pool<<<grid, 128>>>(x, W1, b1, W2, b2, out, P);

    if (has_pids)
        k_pids<<<(P + 255) / 256, 256>>>(out + (size_t)P * D, P);
}

// round 3
// speedup vs baseline: 1.0901x; 1.0901x over previous
#include <cuda_runtime.h>
#include <cstdint>

// ---------------------------------------------------------------------------
// TemporalAttentionPooling (GB300 / sm_103a) — Round 2
//   scores = tanh(x @ W1 + b1) @ W2 + b2            (N,)    MLP: 128 -> 32 -> 1
//   per-segment (sorted person_ids) stable softmax -> weights
//   pooled[p] = sum_i w_i * x_i                     (P, 128)
//   second output: pooled_pids = arange(P)          (P,)  written as float(p)
//
// R2 changes vs R1 (649.8 us):
//   - __launch_bounds__(128,2): 256-reg budget -> no spills of the 128-reg W1
//   - software-pipelined x prefetch in the score phase
//   - 8-deep MLP in the pooling loop
//   - exactly 2 launches per call (setup + main) so ncu -s 5 profiles main
// ---------------------------------------------------------------------------

#define MAX_P 20001
__device__ int g_seg_start[MAX_P];

static __device__ __forceinline__ unsigned long long f2pack(float lo, float hi) {
    unsigned long long r;
    asm("mov.b64 %0, {%1, %2};" : "=l"(r) : "f"(lo), "f"(hi));
    return r;
}
static __device__ __forceinline__ void f2unpack(unsigned long long v, float& lo, float& hi) {
    asm("mov.b64 {%0, %1}, %2;" : "=f"(lo), "=f"(hi) : "l"(v));
}
static __device__ __forceinline__ unsigned long long ffma2(unsigned long long a,
                                                           unsigned long long b,
                                                           unsigned long long c) {
    unsigned long long d;
    asm("fma.rn.f32x2 %0, %1, %2, %3;" : "=l"(d) : "l"(a), "l"(b), "l"(c));
    return d;
}
static __device__ __forceinline__ unsigned long long fadd2(unsigned long long a,
                                                           unsigned long long b) {
    unsigned long long d;
    asm("add.rn.f32x2 %0, %1, %2;" : "=l"(d) : "l"(a), "l"(b));
    return d;
}

// Block-wide reduce over 128 threads. red must hold >= 5 floats.
static __device__ __forceinline__ float blk_reduce(float v, float* red, int tid, bool domax) {
    int lane = tid & 31, wid = tid >> 5;
#pragma unroll
    for (int o = 16; o > 0; o >>= 1) {
        float u = __shfl_xor_sync(0xffffffffu, v, o);
        v = domax ? fmaxf(v, u) : (v + u);
    }
    __syncthreads();               // protects red reuse + publishes prior smem writes
    if (lane == 0) red[wid] = v;
    __syncthreads();
    if (tid == 0) {
        float r = red[0];
#pragma unroll
        for (int w = 1; w < 4; w++) r = domax ? fmaxf(r, red[w]) : (r + red[w]);
        red[4] = r;
    }
    __syncthreads();
    return red[4];
}

// ---- fused setup kernel: segment bounds + pids output ----------------------
__global__ void k_setup(const int* __restrict__ pid, int n, int P,
                        float* __restrict__ outpids) {
    int i = blockIdx.x * blockDim.x + threadIdx.x;
    if (outpids != nullptr && i < P) outpids[i] = (float)i;
    if (i < n) {
        int cur  = pid[i];
        int prev = (i == 0) ? -1 : pid[i - 1];
        for (int q = prev + 1; q <= cur; ++q) g_seg_start[q] = i;
        if (i == n - 1)
            for (int q = cur + 1; q <= P; ++q) g_seg_start[q] = n;
    }
}

// ---- fused main kernel -----------------------------------------------------
#define CHUNK 512

__global__ void __launch_bounds__(128, 2)
seg_attn_pool(const float* __restrict__ x,
              const float* __restrict__ W1,   // (128, 32) row-major
              const float* __restrict__ b1,   // (32,)
              const float* __restrict__ W2,   // (32,)
              const float* __restrict__ b2,   // (1,)
              float* __restrict__ out,        // (P, 128)
              int P) {
    __shared__ __align__(16) float xbuf[4][128];   // per-warp row stage
    __shared__ float sc[CHUNK];                    // chunk scores -> exp weights
    __shared__ float red[5];

    const int tid  = threadIdx.x;
    const int wid  = tid >> 5;
    const int lane = tid & 31;
    const float NEG_INF = __int_as_float(0xff800000u);

    // W1 column `lane` in registers as 64 f32x2 pairs (128 regs, no spills
    // at the 256-reg budget from __launch_bounds__(128,2)).
    unsigned long long w1p[64];
#pragma unroll
    for (int q = 0; q < 64; q++) {
        float lo = W1[(2 * q) * 32 + lane];
        float hi = W1[(2 * q + 1) * 32 + lane];
        w1p[q] = f2pack(lo, hi);
    }
    const float w2j = W2[lane];
    const float b2s = b2[0];
    const unsigned long long b1pair = f2pack(b1[lane], 0.0f);

    for (int p = blockIdx.x; p < P; p += gridDim.x) {
        const int s0 = g_seg_start[p];
        const int s1 = g_seg_start[p + 1];

        float M = NEG_INF;   // running max
        float S = 0.0f;      // running sum of exp
        float acc = 0.0f;    // running pooled accumulator for dim `tid`

        for (int c0 = s0; c0 < s1; c0 += CHUNK) {
            const int cnt = min(CHUNK, s1 - c0);

            // --- scores: warp-per-row, software-pipelined x prefetch ---
            {
                int ci = wid;
                float4 xv;
                if (ci < cnt)
                    xv = reinterpret_cast<const float4*>(x + (size_t)(c0 + ci) * 128)[lane];
                for (; ci < cnt; ci += 4) {
                    reinterpret_cast<float4*>(xbuf[wid])[lane] = xv;
                    __syncwarp();
                    if (ci + 4 < cnt)   // prefetch next row before the FMA chain
                        xv = reinterpret_cast<const float4*>(
                                 x + (size_t)(c0 + ci + 4) * 128)[lane];

                    unsigned long long a0 = b1pair, a1 = 0ull, a2 = 0ull, a3 = 0ull;
                    const ulonglong2* xb = reinterpret_cast<const ulonglong2*>(xbuf[wid]);
#pragma unroll
                    for (int k = 0; k < 32; k++) {
                        ulonglong2 v = xb[k];       // broadcast LDS.128
                        if (k & 1) {
                            a2 = ffma2(v.x, w1p[2 * k],     a2);
                            a3 = ffma2(v.y, w1p[2 * k + 1], a3);
                        } else {
                            a0 = ffma2(v.x, w1p[2 * k],     a0);
                            a1 = ffma2(v.y, w1p[2 * k + 1], a1);
                        }
                    }
                    unsigned long long t = fadd2(fadd2(a0, a2), fadd2(a1, a3));
                    float lo, hi;
                    f2unpack(t, lo, hi);
                    float h  = tanhf(lo + hi);
                    float sv = h * w2j;
#pragma unroll
                    for (int o = 16; o > 0; o >>= 1)
                        sv += __shfl_xor_sync(0xffffffffu, sv, o);
                    if (lane == 0) sc[ci] = sv + b2s;
                    __syncwarp();                   // xbuf WAR before next store
                }
            }
            __syncthreads();

            // --- chunk max, merge into running max ---
            float lm = NEG_INF;
            for (int i = tid; i < cnt; i += 128) lm = fmaxf(lm, sc[i]);
            float mC   = blk_reduce(lm, red, tid, true);
            float newM = fmaxf(M, mC);
            float scale = expf(M - newM);           // M==-inf on first chunk -> 0

            // --- exponentials + chunk sum (write e back into sc) ---
            float ls = 0.0f;
            for (int i = tid; i < cnt; i += 128) {
                float e = expf(sc[i] - newM);
                sc[i] = e;
                ls += e;
            }
            float sC = blk_reduce(ls, red, tid, false);  // syncs publish sc[]
            S = S * scale + sC;
            M = newM;

            // --- pooling: thread owns dim `tid`; rows are L1/L2-hot; MLP=8 ---
            const float* xc = x + (size_t)c0 * 128 + tid;
            float pp0 = 0.f, pp1 = 0.f, pp2 = 0.f, pp3 = 0.f;
            float pp4 = 0.f, pp5 = 0.f, pp6 = 0.f, pp7 = 0.f;
            int i = 0;
            for (; i + 8 <= cnt; i += 8) {
                pp0 += sc[i]     * xc[(size_t)(i)     * 128];
                pp1 += sc[i + 1] * xc[(size_t)(i + 1) * 128];
                pp2 += sc[i + 2] * xc[(size_t)(i + 2) * 128];
                pp3 += sc[i + 3] * xc[(size_t)(i + 3) * 128];
                pp4 += sc[i + 4] * xc[(size_t)(i + 4) * 128];
                pp5 += sc[i + 5] * xc[(size_t)(i + 5) * 128];
                pp6 += sc[i + 6] * xc[(size_t)(i + 6) * 128];
                pp7 += sc[i + 7] * xc[(size_t)(i + 7) * 128];
            }
            for (; i < cnt; i++) pp0 += sc[i] * xc[(size_t)i * 128];
            float psum = ((pp0 + pp1) + (pp2 + pp3)) + ((pp4 + pp5) + (pp6 + pp7));
            acc = acc * scale + psum;

            __syncthreads();                        // sc reuse next chunk
        }

        float denom = (S > 0.0f) ? S : 1.0f;        // empty segment -> 0
        out[(size_t)p * 128 + tid] = acc / denom;
    }
}

// ---------------------------------------------------------------------------
extern "C" void kernel_launch(void* const* d_in, const int* in_sizes, int n_in,
                              void* d_out, int out_size) {
    const float* x   = (const float*)d_in[0];
    const int*   pid = (const int*)  d_in[1];
    const float* W1  = (const float*)d_in[2];
    const float* b1  = (const float*)d_in[3];
    const float* W2  = (const float*)d_in[4];
    const float* b2  = (const float*)d_in[5];
    float* out = (float*)d_out;

    const int n = in_sizes[1];       // N (person_ids count)
    const int D = 128;

    // Output layout: concat(pooled (P,D), pooled_pids (P,)) -> P*(D+1) elems.
    int P;
    bool has_pids;
    if (out_size % (D + 1) == 0) {
        P = out_size / (D + 1);
        has_pids = true;
    } else {
        P = out_size / D;
        has_pids = false;
    }
    if (P > MAX_P - 1) P = MAX_P - 1;   // scratch guard (never hits here)

    float* outpids = has_pids ? (out + (size_t)P * D) : nullptr;
    int cover = (n > P) ? n : P;
    k_setup<<<(cover + 255) / 256, 256>>>(pid, n, P, outpids);

    int grid = 912;                  // persistent-ish, ~18 segments per block
    if (grid > P) grid = P;
    seg_attn_pool<<<grid, 128>>>(x, W1, b1, W2, b2, out, P);
}

// round 4
// speedup vs baseline: 1.7126x; 1.5710x over previous
#include <cuda_runtime.h>
#include <cstdint>

// ---------------------------------------------------------------------------
// TemporalAttentionPooling (GB300 / sm_103a) — Round 3
//   scores = tanh(x @ W1 + b1) @ W2 + b2            (N,)    MLP: 128 -> 32 -> 1
//   per-segment softmax (max-free: scores bounded, exp cannot overflow)
//   pooled[p] = sum_i e_i * x_i / sum_i e_i        (P, 128)
//   pooled_pids = arange(P) written as float
//
// R3 vs R2 (596 us, latency-bound: MLP=1 prefetch + 8 warps/SM):
//   - W1 in smem (f32x2 quads) -> ~100 regs -> 4 blocks/SM (16 warps)
//   - cp.async 8-row double-buffered staging  -> MLP=8, copy/compute overlap
//   - max-free softmax -> pooling fused into score phase, x read from smem,
//     single DRAM pass, no chunk barriers
// ---------------------------------------------------------------------------

#define MAX_P 20001
__device__ int g_seg_start[MAX_P];

static __device__ __forceinline__ unsigned long long f2pack(float lo, float hi) {
    unsigned long long r;
    asm("mov.b64 %0, {%1, %2};" : "=l"(r) : "f"(lo), "f"(hi));
    return r;
}
static __device__ __forceinline__ void f2unpack(unsigned long long v, float& lo, float& hi) {
    asm("mov.b64 {%0, %1}, %2;" : "=f"(lo), "=f"(hi) : "l"(v));
}
static __device__ __forceinline__ unsigned long long ffma2(unsigned long long a,
                                                           unsigned long long b,
                                                           unsigned long long c) {
    unsigned long long d;
    asm("fma.rn.f32x2 %0, %1, %2, %3;" : "=l"(d) : "l"(a), "l"(b), "l"(c));
    return d;
}
static __device__ __forceinline__ unsigned long long fadd2(unsigned long long a,
                                                           unsigned long long b) {
    unsigned long long d;
    asm("add.rn.f32x2 %0, %1, %2;" : "=l"(d) : "l"(a), "l"(b));
    return d;
}

static __device__ __forceinline__ void cp_async16(uint32_t dst, const void* src, int pred) {
    asm volatile(
        "{ .reg .pred p;\n"
        "  setp.ne.u32 p, %2, 0;\n"
        "  @p cp.async.cg.shared.global [%0], [%1], 16; }\n"
        :: "r"(dst), "l"(src), "r"(pred));
}
#define CP_COMMIT() asm volatile("cp.async.commit_group;" ::: "memory")
#define CP_WAIT1()  asm volatile("cp.async.wait_group 1;" ::: "memory")
#define CP_WAIT0()  asm volatile("cp.async.wait_group 0;" ::: "memory")

// ---- setup kernel: segment bounds + pids output ----------------------------
__global__ void k_setup(const int* __restrict__ pid, int n, int P,
                        float* __restrict__ outpids) {
    int i = blockIdx.x * blockDim.x + threadIdx.x;
    if (outpids != nullptr && i < P) outpids[i] = (float)i;
    if (i < n) {
        int cur  = pid[i];
        int prev = (i == 0) ? -1 : pid[i - 1];
        for (int q = prev + 1; q <= cur; ++q) g_seg_start[q] = i;
        if (i == n - 1)
            for (int q = cur + 1; q <= P; ++q) g_seg_start[q] = n;
    }
}

// ---- fused main kernel -----------------------------------------------------
// smem: [0,16K)  W1 as ulonglong2 quads w1q[t=0..31][j=0..31]
//       [16K,48K) xstage: 4 warps x 2 bufs x 8 rows x 128 floats
//       finalize aliases each warp's own xstage area (safe: compute done)

__global__ void __launch_bounds__(128, 4)
seg_attn_pool(const float* __restrict__ x,
              const float* __restrict__ W1,   // (128, 32) row-major
              const float* __restrict__ b1,   // (32,)
              const float* __restrict__ W2,   // (32,)
              const float* __restrict__ b2,   // (1,)
              float* __restrict__ out,        // (P, 128)
              int P) {
    static __shared__ __align__(16) char smem_raw[49152];
    ulonglong2* w1q = reinterpret_cast<ulonglong2*>(smem_raw);
    float*      xs  = reinterpret_cast<float*>(smem_raw + 16384);

    const int tid  = threadIdx.x;
    const int wid  = tid >> 5;
    const int lane = tid & 31;

    // Pack W1 into f32x2 quads: w1q[t*32+j] = {(W1[4t][j],W1[4t+1][j]),
    //                                          (W1[4t+2][j],W1[4t+3][j])}
    for (int idx = tid; idx < 4096; idx += 128) {
        int k = idx >> 5, j = idx & 31;
        reinterpret_cast<float*>(&w1q[(k >> 2) * 32 + j])[k & 3] = W1[idx];
    }
    const float w2j = W2[lane];
    const float b2s = b2[0];
    const unsigned long long b1pair = f2pack(b1[lane], 0.0f);
    __syncthreads();

    // byte address of this warp's staging area (2 bufs x 4096B)
    const uint32_t xs_sh =
        (uint32_t)__cvta_generic_to_shared(xs) + (uint32_t)wid * 8192u;
    float* const xsw = xs + wid * 2048;     // float view of same area

    for (int p = blockIdx.x; p < P; p += gridDim.x) {
        const int s0 = g_seg_start[p];
        const int s1 = g_seg_start[p + 1];

        unsigned long long pa0 = 0ull, pa1 = 0ull;  // pooled dims 4*lane..+3
        float Ssum = 0.0f;                           // sum of exp (lane-replicated)

        int g = s0 + wid * 8;
        int buf = 0;
        if (g < s1) {
#pragma unroll
            for (int r = 0; r < 8; r++)
                cp_async16(xs_sh + (uint32_t)(r * 512 + lane * 16),
                           x + (size_t)(g + r) * 128 + lane * 4, (g + r) < s1);
            CP_COMMIT();
        }

        for (; g < s1; g += 32) {
            const int gn = g + 32;
            if (gn < s1) {
                const uint32_t nb = xs_sh + (uint32_t)((buf ^ 1) * 4096);
#pragma unroll
                for (int r = 0; r < 8; r++)
                    cp_async16(nb + (uint32_t)(r * 512 + lane * 16),
                               x + (size_t)(gn + r) * 128 + lane * 4, (gn + r) < s1);
                CP_COMMIT();
                CP_WAIT1();
            } else {
                CP_WAIT0();
            }
            __syncwarp();

            const int rows = min(8, s1 - g);
            const float* xb = xsw + buf * 1024;

            unsigned long long a0[8], a1[8];
#pragma unroll
            for (int r = 0; r < 8; r++) { a0[r] = b1pair; a1[r] = 0ull; }

#pragma unroll
            for (int t = 0; t < 32; t++) {
                ulonglong2 w = w1q[t * 32 + lane];
#pragma unroll
                for (int r = 0; r < 8; r++) {
                    ulonglong2 xq = *reinterpret_cast<const ulonglong2*>(xb + r * 128 + t * 4);
                    a0[r] = ffma2(xq.x, w.x, a0[r]);
                    a1[r] = ffma2(xq.y, w.y, a1[r]);
                }
            }

#pragma unroll
            for (int r = 0; r < 8; r++) {
                if (r < rows) {
                    float lo, hi;
                    f2unpack(fadd2(a0[r], a1[r]), lo, hi);
                    float sv = tanhf(lo + hi) * w2j;
#pragma unroll
                    for (int o = 16; o > 0; o >>= 1)
                        sv += __shfl_xor_sync(0xffffffffu, sv, o);
                    float e = expf(sv + b2s);       // bounded: no overflow
                    Ssum += e;
                    ulonglong2 xq =
                        *reinterpret_cast<const ulonglong2*>(xb + r * 128 + lane * 4);
                    unsigned long long eq = f2pack(e, e);
                    pa0 = ffma2(xq.x, eq, pa0);
                    pa1 = ffma2(xq.y, eq, pa1);
                }
            }
            buf ^= 1;
        }

        // ---- finalize: combine 4 warps' partials via this warp's xstage ----
        float4 pv;
        f2unpack(pa0, pv.x, pv.y);
        f2unpack(pa1, pv.z, pv.w);
        *reinterpret_cast<float4*>(xsw + 4 * lane) = pv;   // dims 4l..4l+3
        if (lane == 0) xsw[128] = Ssum;
        __syncthreads();

        float v  = xs[tid]       + xs[2048 + tid]
                 + xs[4096 + tid] + xs[6144 + tid];
        float St = xs[128]       + xs[2048 + 128]
                 + xs[4096 + 128] + xs[6144 + 128];
        out[(size_t)p * 128 + tid] = v / ((St > 0.0f) ? St : 1.0f);
        __syncthreads();    // WAR: next segment reuses xstage
    }
}

// ---------------------------------------------------------------------------
extern "C" void kernel_launch(void* const* d_in, const int* in_sizes, int n_in,
                              void* d_out, int out_size) {
    const float* x   = (const float*)d_in[0];
    const int*   pid = (const int*)  d_in[1];
    const float* W1  = (const float*)d_in[2];
    const float* b1  = (const float*)d_in[3];
    const float* W2  = (const float*)d_in[4];
    const float* b2  = (const float*)d_in[5];
    float* out = (float*)d_out;

    const int n = in_sizes[1];       // N (person_ids count)
    const int D = 128;

    int P;
    bool has_pids;
    if (out_size % (D + 1) == 0) { P = out_size / (D + 1); has_pids = true; }
    else                         { P = out_size / D;       has_pids = false; }
    if (P > MAX_P - 1) P = MAX_P - 1;

    float* outpids = has_pids ? (out + (size_t)P * D) : nullptr;
    int cover = (n > P) ? n : P;
    k_setup<<<(cover + 255) / 256, 256>>>(pid, n, P, outpids);

    int grid = 608;                  // 4 blocks/SM x 152 SMs
    if (grid > P) grid = P;
    seg_attn_pool<<<grid, 128>>>(x, W1, b1, W2, b2, out, P);
}

// round 5
// speedup vs baseline: 1.8745x; 1.0945x over previous
#include <cuda_runtime.h>
#include <cstdint>

// ---------------------------------------------------------------------------
// TemporalAttentionPooling (GB300 / sm_103a) — Round 4
//   scores = tanh(x @ W1 + b1) @ W2 + b2            (N,)    MLP: 128 -> 32 -> 1
//   per-segment softmax (max-free: scores bounded, exp cannot overflow)
//   pooled[p] = sum_i e_i * x_i / sum_i e_i        (P, 128)
//   pooled_pids = arange(P) written as float
//
// R4 vs R3 (379 us, L1/crossbar-bound at 81%):
//   - register-tiled warp GEMM: lane (r2=lane>>3, j2=lane&7) computes a
//     2-row x 4-hidden tile; one x LDS.128 now feeds 4 rows (was 1) ->
//     MLP LDS wavefronts 48 -> 24 per row (total ~56 -> ~32)
//   - W1 smem table pre-paired along k (f32x2), no pack instrs in hot loop
//   - XOR swizzle (pos = t ^ r) on the x stage -> conflict-free 4-row gather
// ---------------------------------------------------------------------------

#define MAX_P 20001
__device__ int g_seg_start[MAX_P];

static __device__ __forceinline__ unsigned long long f2pack(float lo, float hi) {
    unsigned long long r;
    asm("mov.b64 %0, {%1, %2};" : "=l"(r) : "f"(lo), "f"(hi));
    return r;
}
static __device__ __forceinline__ void f2unpack(unsigned long long v, float& lo, float& hi) {
    asm("mov.b64 {%0, %1}, %2;" : "=f"(lo), "=f"(hi) : "l"(v));
}
static __device__ __forceinline__ unsigned long long ffma2(unsigned long long a,
                                                           unsigned long long b,
                                                           unsigned long long c) {
    unsigned long long d;
    asm("fma.rn.f32x2 %0, %1, %2, %3;" : "=l"(d) : "l"(a), "l"(b), "l"(c));
    return d;
}

static __device__ __forceinline__ void cp_async16(uint32_t dst, const void* src, int pred) {
    asm volatile(
        "{ .reg .pred p;\n"
        "  setp.ne.u32 p, %2, 0;\n"
        "  @p cp.async.cg.shared.global [%0], [%1], 16; }\n"
        :: "r"(dst), "l"(src), "r"(pred));
}
#define CP_COMMIT() asm volatile("cp.async.commit_group;" ::: "memory")
#define CP_WAIT1()  asm volatile("cp.async.wait_group 1;" ::: "memory")
#define CP_WAIT0()  asm volatile("cp.async.wait_group 0;" ::: "memory")

// ---- setup kernel: segment bounds + pids output ----------------------------
__global__ void k_setup(const int* __restrict__ pid, int n, int P,
                        float* __restrict__ outpids) {
    int i = blockIdx.x * blockDim.x + threadIdx.x;
    if (outpids != nullptr && i < P) outpids[i] = (float)i;
    if (i < n) {
        int cur  = pid[i];
        int prev = (i == 0) ? -1 : pid[i - 1];
        for (int q = prev + 1; q <= cur; ++q) g_seg_start[q] = i;
        if (i == n - 1)
            for (int q = cur + 1; q <= P; ++q) g_seg_start[q] = n;
    }
}

// ---- fused main kernel -----------------------------------------------------
// smem layout (48 KB total):
//   [0, 16K)   w1t: ulonglong2[1024]; q = kp*16 + part*8 + j2
//              .x = {W1[2kp][j0], W1[2kp+1][j0]}, .y = same for j0+1,
//              j0 = 4*j2 + 2*part   (k-pairs pre-packed for f32x2 FMA)
//   [16K,48K)  xstage: 4 warps x 2 bufs x 8 rows x 128 floats
//              row r stores 16B chunk c at position (c ^ r)  [XOR swizzle]

__global__ void __launch_bounds__(128, 4)
seg_attn_pool(const float* __restrict__ x,
              const float* __restrict__ W1,   // (128, 32) row-major
              const float* __restrict__ b1,   // (32,)
              const float* __restrict__ W2,   // (32,)
              const float* __restrict__ b2,   // (1,)
              float* __restrict__ out,        // (P, 128)
              int P) {
    static __shared__ __align__(16) char smem_raw[49152];
    ulonglong2* w1t = reinterpret_cast<ulonglong2*>(smem_raw);
    float*      xs  = reinterpret_cast<float*>(smem_raw + 16384);

    const int tid  = threadIdx.x;
    const int wid  = tid >> 5;
    const int lane = tid & 31;
    const int j2   = lane & 7;      // hidden-unit group: j = 4*j2 .. 4*j2+3
    const int r2   = lane >> 3;     // row group: rows r2 and r2+4

    // Build the k-paired W1 table (one-time).
    {
        float* w1f = reinterpret_cast<float*>(w1t);
        for (int q4 = tid; q4 < 4096; q4 += 128) {
            int q    = q4 >> 2, slot = q4 & 3;
            int kp   = q >> 4, rem = q & 15;
            int part = rem >> 3, jq = rem & 7;
            int j    = 4 * jq + 2 * part + (slot >> 1);
            int krow = 2 * kp + (slot & 1);
            w1f[q4] = W1[krow * 32 + j];
        }
    }
    const float4 b1q = reinterpret_cast<const float4*>(b1)[j2];
    const float4 w2q = reinterpret_cast<const float4*>(W2)[j2];
    const float  b2s = b2[0];
    __syncthreads();

    // this warp's staging area: 2 bufs x 4 KB
    const uint32_t xs_sh =
        (uint32_t)__cvta_generic_to_shared(xs) + (uint32_t)wid * 8192u;
    float* const xsw = xs + wid * 2048;

    for (int p = blockIdx.x; p < P; p += gridDim.x) {
        const int s0 = g_seg_start[p];
        const int s1 = g_seg_start[p + 1];

        unsigned long long pa0 = 0ull, pa1 = 0ull;  // pooled dims 4*lane..+3
        float Ssum = 0.0f;                           // lane-replicated

        int g = s0 + wid * 8;
        int buf = 0;
        if (g < s1) {
#pragma unroll
            for (int r = 0; r < 8; r++)
                cp_async16(xs_sh + (uint32_t)(r * 512 + ((lane ^ r) * 16)),
                           x + (size_t)(g + r) * 128 + lane * 4, (g + r) < s1);
            CP_COMMIT();
        }

        for (; g < s1; g += 32) {
            const int gn = g + 32;
            if (gn < s1) {
                const uint32_t nb = xs_sh + (uint32_t)((buf ^ 1) * 4096);
#pragma unroll
                for (int r = 0; r < 8; r++)
                    cp_async16(nb + (uint32_t)(r * 512 + ((lane ^ r) * 16)),
                               x + (size_t)(gn + r) * 128 + lane * 4, (gn + r) < s1);
                CP_COMMIT();
                CP_WAIT1();
            } else {
                CP_WAIT0();
            }
            __syncwarp();

            const int rows = min(8, s1 - g);
            const float* xb = xsw + buf * 1024;
            const float* xbA = xb + r2 * 128;          // row r2
            const float* xbB = xb + (r2 + 4) * 128;    // row r2+4

            // 2-row x 4-hidden accumulators, f32x2 over k-pairs
            unsigned long long accA[4] = {0ull, 0ull, 0ull, 0ull};
            unsigned long long accB[4] = {0ull, 0ull, 0ull, 0ull};

#pragma unroll
            for (int t = 0; t < 32; t++) {
                // x chunk t of each row (swizzled position t^r): 4 k-values
                ulonglong2 xqA = *reinterpret_cast<const ulonglong2*>(
                                     xbA + ((t ^ r2) << 2));
                ulonglong2 xqB = *reinterpret_cast<const ulonglong2*>(
                                     xbB + ((t ^ (r2 + 4)) << 2));
                // W1 k-pairs for this chunk, this lane's 4 hidden units
                ulonglong2 wA0 = w1t[32 * t + j2];          // kp=2t,  j 4j2..4j2+1
                ulonglong2 wA1 = w1t[32 * t + 8 + j2];      // kp=2t,  j 4j2+2..+3
                ulonglong2 wB0 = w1t[32 * t + 16 + j2];     // kp=2t+1, low js
                ulonglong2 wB1 = w1t[32 * t + 24 + j2];     // kp=2t+1, high js

                accA[0] = ffma2(xqA.x, wA0.x, accA[0]);
                accA[1] = ffma2(xqA.x, wA0.y, accA[1]);
                accA[2] = ffma2(xqA.x, wA1.x, accA[2]);
                accA[3] = ffma2(xqA.x, wA1.y, accA[3]);
                accA[0] = ffma2(xqA.y, wB0.x, accA[0]);
                accA[1] = ffma2(xqA.y, wB0.y, accA[1]);
                accA[2] = ffma2(xqA.y, wB1.x, accA[2]);
                accA[3] = ffma2(xqA.y, wB1.y, accA[3]);

                accB[0] = ffma2(xqB.x, wA0.x, accB[0]);
                accB[1] = ffma2(xqB.x, wA0.y, accB[1]);
                accB[2] = ffma2(xqB.x, wA1.x, accB[2]);
                accB[3] = ffma2(xqB.x, wA1.y, accB[3]);
                accB[0] = ffma2(xqB.y, wB0.x, accB[0]);
                accB[1] = ffma2(xqB.y, wB0.y, accB[1]);
                accB[2] = ffma2(xqB.y, wB1.x, accB[2]);
                accB[3] = ffma2(xqB.y, wB1.y, accB[3]);
            }

            // finish hidden units: tanh + dot with W2 (lane's 4 js)
            float pA = 0.0f, pB = 0.0f;
#pragma unroll
            for (int jj = 0; jj < 4; jj++) {
                float lo, hi;
                f2unpack(accA[jj], lo, hi);
                float hA = lo + hi + reinterpret_cast<const float*>(&b1q)[jj];
                pA += tanhf(hA) * reinterpret_cast<const float*>(&w2q)[jj];
                f2unpack(accB[jj], lo, hi);
                float hB = lo + hi + reinterpret_cast<const float*>(&b1q)[jj];
                pB += tanhf(hB) * reinterpret_cast<const float*>(&w2q)[jj];
            }
            // reduce over j2 (8 lanes)
#pragma unroll
            for (int o = 1; o < 8; o <<= 1) {
                pA += __shfl_xor_sync(0xffffffffu, pA, o);
                pB += __shfl_xor_sync(0xffffffffu, pB, o);
            }
            float eA = expf(pA + b2s);   // score row r2   (bounded, no overflow)
            float eB = expf(pB + b2s);   // score row r2+4

            // pooling: lane owns dims 4*lane..4*lane+3
#pragma unroll
            for (int r = 0; r < 8; r++) {
                if (r < rows) {
                    float ew = __shfl_sync(0xffffffffu, (r < 4) ? eA : eB,
                                           (r & 3) * 8);
                    Ssum += ew;
                    ulonglong2 xq = *reinterpret_cast<const ulonglong2*>(
                                        xb + r * 128 + ((lane ^ r) << 2));
                    unsigned long long eq = f2pack(ew, ew);
                    pa0 = ffma2(xq.x, eq, pa0);
                    pa1 = ffma2(xq.y, eq, pa1);
                }
            }
            buf ^= 1;
        }

        // ---- finalize: combine 4 warps' partials via warp's own xstage ----
        float4 pv;
        f2unpack(pa0, pv.x, pv.y);
        f2unpack(pa1, pv.z, pv.w);
        *reinterpret_cast<float4*>(xsw + 4 * lane) = pv;   // dims 4l..4l+3
        if (lane == 0) xsw[128] = Ssum;
        __syncthreads();

        float v  = xs[tid]        + xs[2048 + tid]
                 + xs[4096 + tid] + xs[6144 + tid];
        float St = xs[128]        + xs[2048 + 128]
                 + xs[4096 + 128] + xs[6144 + 128];
        out[(size_t)p * 128 + tid] = v / ((St > 0.0f) ? St : 1.0f);
        __syncthreads();    // WAR: next segment reuses xstage
    }
}

// ---------------------------------------------------------------------------
extern "C" void kernel_launch(void* const* d_in, const int* in_sizes, int n_in,
                              void* d_out, int out_size) {
    const float* x   = (const float*)d_in[0];
    const int*   pid = (const int*)  d_in[1];
    const float* W1  = (const float*)d_in[2];
    const float* b1  = (const float*)d_in[3];
    const float* W2  = (const float*)d_in[4];
    const float* b2  = (const float*)d_in[5];
    float* out = (float*)d_out;

    const int n = in_sizes[1];       // N (person_ids count)
    const int D = 128;

    int P;
    bool has_pids;
    if (out_size % (D + 1) == 0) { P = out_size / (D + 1); has_pids = true; }
    else                         { P = out_size / D;       has_pids = false; }
    if (P > MAX_P - 1) P = MAX_P - 1;

    float* outpids = has_pids ? (out + (size_t)P * D) : nullptr;
    int cover = (n > P) ? n : P;
    k_setup<<<(cover + 255) / 256, 256>>>(pid, n, P, outpids);

    int grid = 608;                  // 4 blocks/SM x 152 SMs
    if (grid > P) grid = P;
    seg_attn_pool<<<grid, 128>>>(x, W1, b1, W2, b2, out, P);
}

// round 6
// speedup vs baseline: 1.8768x; 1.0012x over previous
#include <cuda_runtime.h>
#include <cstdint>

// ---------------------------------------------------------------------------
// TemporalAttentionPooling (GB300 / sm_103a) — Round 4
//   scores = tanh(x @ W1 + b1) @ W2 + b2            (N,)    MLP: 128 -> 32 -> 1
//   per-segment softmax (max-free: scores bounded, exp cannot overflow)
//   pooled[p] = sum_i e_i * x_i / sum_i e_i        (P, 128)
//   pooled_pids = arange(P) written as float
//
// R4 vs R3 (379 us, L1/crossbar-bound at 81%):
//   - register-tiled warp GEMM: lane (r2=lane>>3, j2=lane&7) computes a
//     2-row x 4-hidden tile; one x LDS.128 now feeds 4 rows (was 1) ->
//     MLP LDS wavefronts 48 -> 24 per row (total ~56 -> ~32)
//   - W1 smem table pre-paired along k (f32x2), no pack instrs in hot loop
//   - XOR swizzle (pos = t ^ r) on the x stage -> conflict-free 4-row gather
// ---------------------------------------------------------------------------

#define MAX_P 20001
__device__ int g_seg_start[MAX_P];

static __device__ __forceinline__ unsigned long long f2pack(float lo, float hi) {
    unsigned long long r;
    asm("mov.b64 %0, {%1, %2};" : "=l"(r) : "f"(lo), "f"(hi));
    return r;
}
static __device__ __forceinline__ void f2unpack(unsigned long long v, float& lo, float& hi) {
    asm("mov.b64 {%0, %1}, %2;" : "=f"(lo), "=f"(hi) : "l"(v));
}
static __device__ __forceinline__ unsigned long long ffma2(unsigned long long a,
                                                           unsigned long long b,
                                                           unsigned long long c) {
    unsigned long long d;
    asm("fma.rn.f32x2 %0, %1, %2, %3;" : "=l"(d) : "l"(a), "l"(b), "l"(c));
    return d;
}

static __device__ __forceinline__ void cp_async16(uint32_t dst, const void* src, int pred) {
    asm volatile(
        "{ .reg .pred p;\n"
        "  setp.ne.u32 p, %2, 0;\n"
        "  @p cp.async.cg.shared.global [%0], [%1], 16; }\n"
        :: "r"(dst), "l"(src), "r"(pred));
}
#define CP_COMMIT() asm volatile("cp.async.commit_group;" ::: "memory")
#define CP_WAIT1()  asm volatile("cp.async.wait_group 1;" ::: "memory")
#define CP_WAIT0()  asm volatile("cp.async.wait_group 0;" ::: "memory")

// ---- setup kernel: segment bounds + pids output ----------------------------
__global__ void k_setup(const int* __restrict__ pid, int n, int P,
                        float* __restrict__ outpids) {
    int i = blockIdx.x * blockDim.x + threadIdx.x;
    if (outpids != nullptr && i < P) outpids[i] = (float)i;
    if (i < n) {
        int cur  = pid[i];
        int prev = (i == 0) ? -1 : pid[i - 1];
        for (int q = prev + 1; q <= cur; ++q) g_seg_start[q] = i;
        if (i == n - 1)
            for (int q = cur + 1; q <= P; ++q) g_seg_start[q] = n;
    }
}

// ---- fused main kernel -----------------------------------------------------
// smem layout (48 KB total):
//   [0, 16K)   w1t: ulonglong2[1024]; q = kp*16 + part*8 + j2
//              .x = {W1[2kp][j0], W1[2kp+1][j0]}, .y = same for j0+1,
//              j0 = 4*j2 + 2*part   (k-pairs pre-packed for f32x2 FMA)
//   [16K,48K)  xstage: 4 warps x 2 bufs x 8 rows x 128 floats
//              row r stores 16B chunk c at position (c ^ r)  [XOR swizzle]

__global__ void __launch_bounds__(128, 4)
seg_attn_pool(const float* __restrict__ x,
              const float* __restrict__ W1,   // (128, 32) row-major
              const float* __restrict__ b1,   // (32,)
              const float* __restrict__ W2,   // (32,)
              const float* __restrict__ b2,   // (1,)
              float* __restrict__ out,        // (P, 128)
              int P) {
    static __shared__ __align__(16) char smem_raw[49152];
    ulonglong2* w1t = reinterpret_cast<ulonglong2*>(smem_raw);
    float*      xs  = reinterpret_cast<float*>(smem_raw + 16384);

    const int tid  = threadIdx.x;
    const int wid  = tid >> 5;
    const int lane = tid & 31;
    const int j2   = lane & 7;      // hidden-unit group: j = 4*j2 .. 4*j2+3
    const int r2   = lane >> 3;     // row group: rows r2 and r2+4

    // Build the k-paired W1 table (one-time).
    {
        float* w1f = reinterpret_cast<float*>(w1t);
        for (int q4 = tid; q4 < 4096; q4 += 128) {
            int q    = q4 >> 2, slot = q4 & 3;
            int kp   = q >> 4, rem = q & 15;
            int part = rem >> 3, jq = rem & 7;
            int j    = 4 * jq + 2 * part + (slot >> 1);
            int krow = 2 * kp + (slot & 1);
            w1f[q4] = W1[krow * 32 + j];
        }
    }
    const float4 b1q = reinterpret_cast<const float4*>(b1)[j2];
    const float4 w2q = reinterpret_cast<const float4*>(W2)[j2];
    const float  b2s = b2[0];
    __syncthreads();

    // this warp's staging area: 2 bufs x 4 KB
    const uint32_t xs_sh =
        (uint32_t)__cvta_generic_to_shared(xs) + (uint32_t)wid * 8192u;
    float* const xsw = xs + wid * 2048;

    for (int p = blockIdx.x; p < P; p += gridDim.x) {
        const int s0 = g_seg_start[p];
        const int s1 = g_seg_start[p + 1];

        unsigned long long pa0 = 0ull, pa1 = 0ull;  // pooled dims 4*lane..+3
        float Ssum = 0.0f;                           // lane-replicated

        int g = s0 + wid * 8;
        int buf = 0;
        if (g < s1) {
#pragma unroll
            for (int r = 0; r < 8; r++)
                cp_async16(xs_sh + (uint32_t)(r * 512 + ((lane ^ r) * 16)),
                           x + (size_t)(g + r) * 128 + lane * 4, (g + r) < s1);
            CP_COMMIT();
        }

        for (; g < s1; g += 32) {
            const int gn = g + 32;
            if (gn < s1) {
                const uint32_t nb = xs_sh + (uint32_t)((buf ^ 1) * 4096);
#pragma unroll
                for (int r = 0; r < 8; r++)
                    cp_async16(nb + (uint32_t)(r * 512 + ((lane ^ r) * 16)),
                               x + (size_t)(gn + r) * 128 + lane * 4, (gn + r) < s1);
                CP_COMMIT();
                CP_WAIT1();
            } else {
                CP_WAIT0();
            }
            __syncwarp();

            const int rows = min(8, s1 - g);
            const float* xb = xsw + buf * 1024;
            const float* xbA = xb + r2 * 128;          // row r2
            const float* xbB = xb + (r2 + 4) * 128;    // row r2+4

            // 2-row x 4-hidden accumulators, f32x2 over k-pairs
            unsigned long long accA[4] = {0ull, 0ull, 0ull, 0ull};
            unsigned long long accB[4] = {0ull, 0ull, 0ull, 0ull};

#pragma unroll
            for (int t = 0; t < 32; t++) {
                // x chunk t of each row (swizzled position t^r): 4 k-values
                ulonglong2 xqA = *reinterpret_cast<const ulonglong2*>(
                                     xbA + ((t ^ r2) << 2));
                ulonglong2 xqB = *reinterpret_cast<const ulonglong2*>(
                                     xbB + ((t ^ (r2 + 4)) << 2));
                // W1 k-pairs for this chunk, this lane's 4 hidden units
                ulonglong2 wA0 = w1t[32 * t + j2];          // kp=2t,  j 4j2..4j2+1
                ulonglong2 wA1 = w1t[32 * t + 8 + j2];      // kp=2t,  j 4j2+2..+3
                ulonglong2 wB0 = w1t[32 * t + 16 + j2];     // kp=2t+1, low js
                ulonglong2 wB1 = w1t[32 * t + 24 + j2];     // kp=2t+1, high js

                accA[0] = ffma2(xqA.x, wA0.x, accA[0]);
                accA[1] = ffma2(xqA.x, wA0.y, accA[1]);
                accA[2] = ffma2(xqA.x, wA1.x, accA[2]);
                accA[3] = ffma2(xqA.x, wA1.y, accA[3]);
                accA[0] = ffma2(xqA.y, wB0.x, accA[0]);
                accA[1] = ffma2(xqA.y, wB0.y, accA[1]);
                accA[2] = ffma2(xqA.y, wB1.x, accA[2]);
                accA[3] = ffma2(xqA.y, wB1.y, accA[3]);

                accB[0] = ffma2(xqB.x, wA0.x, accB[0]);
                accB[1] = ffma2(xqB.x, wA0.y, accB[1]);
                accB[2] = ffma2(xqB.x, wA1.x, accB[2]);
                accB[3] = ffma2(xqB.x, wA1.y, accB[3]);
                accB[0] = ffma2(xqB.y, wB0.x, accB[0]);
                accB[1] = ffma2(xqB.y, wB0.y, accB[1]);
                accB[2] = ffma2(xqB.y, wB1.x, accB[2]);
                accB[3] = ffma2(xqB.y, wB1.y, accB[3]);
            }

            // finish hidden units: tanh + dot with W2 (lane's 4 js)
            float pA = 0.0f, pB = 0.0f;
#pragma unroll
            for (int jj = 0; jj < 4; jj++) {
                float lo, hi;
                f2unpack(accA[jj], lo, hi);
                float hA = lo + hi + reinterpret_cast<const float*>(&b1q)[jj];
                pA += tanhf(hA) * reinterpret_cast<const float*>(&w2q)[jj];
                f2unpack(accB[jj], lo, hi);
                float hB = lo + hi + reinterpret_cast<const float*>(&b1q)[jj];
                pB += tanhf(hB) * reinterpret_cast<const float*>(&w2q)[jj];
            }
            // reduce over j2 (8 lanes)
#pragma unroll
            for (int o = 1; o < 8; o <<= 1) {
                pA += __shfl_xor_sync(0xffffffffu, pA, o);
                pB += __shfl_xor_sync(0xffffffffu, pB, o);
            }
            float eA = expf(pA + b2s);   // score row r2   (bounded, no overflow)
            float eB = expf(pB + b2s);   // score row r2+4

            // pooling: lane owns dims 4*lane..4*lane+3
#pragma unroll
            for (int r = 0; r < 8; r++) {
                if (r < rows) {
                    float ew = __shfl_sync(0xffffffffu, (r < 4) ? eA : eB,
                                           (r & 3) * 8);
                    Ssum += ew;
                    ulonglong2 xq = *reinterpret_cast<const ulonglong2*>(
                                        xb + r * 128 + ((lane ^ r) << 2));
                    unsigned long long eq = f2pack(ew, ew);
                    pa0 = ffma2(xq.x, eq, pa0);
                    pa1 = ffma2(xq.y, eq, pa1);
                }
            }
            buf ^= 1;
        }

        // ---- finalize: combine 4 warps' partials via warp's own xstage ----
        float4 pv;
        f2unpack(pa0, pv.x, pv.y);
        f2unpack(pa1, pv.z, pv.w);
        *reinterpret_cast<float4*>(xsw + 4 * lane) = pv;   // dims 4l..4l+3
        if (lane == 0) xsw[128] = Ssum;
        __syncthreads();

        float v  = xs[tid]        + xs[2048 + tid]
                 + xs[4096 + tid] + xs[6144 + tid];
        float St = xs[128]        + xs[2048 + 128]
                 + xs[4096 + 128] + xs[6144 + 128];
        out[(size_t)p * 128 + tid] = v / ((St > 0.0f) ? St : 1.0f);
        __syncthreads();    // WAR: next segment reuses xstage
    }
}

// ---------------------------------------------------------------------------
extern "C" void kernel_launch(void* const* d_in, const int* in_sizes, int n_in,
                              void* d_out, int out_size) {
    const float* x   = (const float*)d_in[0];
    const int*   pid = (const int*)  d_in[1];
    const float* W1  = (const float*)d_in[2];
    const float* b1  = (const float*)d_in[3];
    const float* W2  = (const float*)d_in[4];
    const float* b2  = (const float*)d_in[5];
    float* out = (float*)d_out;

    const int n = in_sizes[1];       // N (person_ids count)
    const int D = 128;

    int P;
    bool has_pids;
    if (out_size % (D + 1) == 0) { P = out_size / (D + 1); has_pids = true; }
    else                         { P = out_size / D;       has_pids = false; }
    if (P > MAX_P - 1) P = MAX_P - 1;

    float* outpids = has_pids ? (out + (size_t)P * D) : nullptr;
    int cover = (n > P) ? n : P;
    k_setup<<<(cover + 255) / 256, 256>>>(pid, n, P, outpids);

    int grid = 608;                  // 4 blocks/SM x 152 SMs
    if (grid > P) grid = P;
    seg_attn_pool<<<grid, 128>>>(x, W1, b1, W2, b2, out, P);
}